// round 13
// baseline (speedup 1.0000x reference)
#include <cuda_runtime.h>
#include <math.h>
#include <stdint.h>

// Problem constants
#define B_  2
#define S_  2048
#define D_  640        // = H_*DH_
#define H_  8
#define DH_ 80
#define M_  (B_*S_)    // 4096

// Scratch (device globals — no allocations allowed)
static __device__ float g_q[M_*D_];
static __device__ float g_k[M_*D_];
static __device__ float g_v[M_*D_];
static __device__ float g_attn[M_*D_];

// ---------------------------------------------------------------------------
// Common tensor-core helpers (tf32 m16n8k8 mma.sync, fp32 accumulate)
// ---------------------------------------------------------------------------
__device__ __forceinline__ float to_tf32(float x) {
    uint32_t u;
    asm("cvt.rna.tf32.f32 %0, %1;" : "=r"(u) : "f"(x));
    return __uint_as_float(u);
}

__device__ __forceinline__ float ex2(float x) {
    float r;
    asm("ex2.approx.ftz.f32 %0, %1;" : "=f"(r) : "f"(x));
    return r;
}

__device__ __forceinline__ void mma_tf32(float c[4],
    float a0, float a1, float a2, float a3, float b0, float b1)
{
    asm volatile(
        "mma.sync.aligned.m16n8k8.row.col.f32.tf32.tf32.f32 "
        "{%0,%1,%2,%3}, {%4,%5,%6,%7}, {%8,%9}, {%0,%1,%2,%3};"
        : "+f"(c[0]), "+f"(c[1]), "+f"(c[2]), "+f"(c[3])
        : "r"(__float_as_uint(a0)), "r"(__float_as_uint(a1)),
          "r"(__float_as_uint(a2)), "r"(__float_as_uint(a3)),
          "r"(__float_as_uint(b0)), "r"(__float_as_uint(b1)));
}

__device__ __forceinline__ float2 tf32_split(float x) {
    float hi = to_tf32(x);
    float lo = to_tf32(x - hi);
    return make_float2(hi, lo);
}

// ---------------------------------------------------------------------------
// Split-tf32 GEMM (fp32-accurate: Ahi*Bhi + Alo*Bhi + Ahi*Blo).
// C[M,N] = A[M,K] @ W[K,N] (+bias). Tile 128x64x16, 256 threads = 8 warps,
// warp tile 32x32 (2 m-frags x 4 n-frags). hi/lo interleaved as float2 in
// smem so each fragment element is a single LDS.64.
// ---------------------------------------------------------------------------
#define GM 128
#define GN 64
#define GK 16
#define AP 18   // float2 per As2 row (16 + pad)
#define WP 18

__global__ __launch_bounds__(256) void gemm_tf32_split(
    const float* __restrict__ A, const float* __restrict__ W,
    const float* __restrict__ bias, float* __restrict__ C,
    int Kdim, int Ndim)
{
    __shared__ float2 As2[GM][AP];   // [m][k] -> (hi,lo)
    __shared__ float2 Ws2[GN][WP];   // [n][k] -> (hi,lo)  (W transposed)

    const int tid  = threadIdx.x;
    const int w    = tid >> 5;
    const int lane = tid & 31;
    const int qr   = lane >> 2;
    const int qc   = lane & 3;
    const int wm   = (w & 3) * 32;   // 4 warps across M
    const int wn   = (w >> 2) * 32;  // 2 warps across N
    const int bm   = blockIdx.y * GM;
    const int bn   = blockIdx.x * GN;

    // gmem load assignment
    const int arow = tid >> 1;          // 0..127
    const int acg  = (tid & 1) * 8;     // k sub-block 0 or 8
    const int wrow = tid >> 4;          // 0..15 (k row of W)
    const int wng  = (tid & 15) * 4;    // n group

    float4 pa0, pa1, pw0;

    float c[2][4][4];
#pragma unroll
    for (int mb = 0; mb < 2; mb++)
#pragma unroll
        for (int nb = 0; nb < 4; nb++)
#pragma unroll
            for (int r = 0; r < 4; r++) c[mb][nb][r] = 0.f;

    // prefetch chunk 0
    pa0 = *(const float4*)(A + (size_t)(bm + arow) * Kdim + acg);
    pa1 = *(const float4*)(A + (size_t)(bm + arow) * Kdim + acg + 4);
    pw0 = *(const float4*)(W + (size_t)wrow * Ndim + bn + wng);

    for (int k0 = 0; k0 < Kdim; k0 += GK) {
        // stage current chunk to smem (hi/lo split on the way)
        As2[arow][acg + 0] = tf32_split(pa0.x);
        As2[arow][acg + 1] = tf32_split(pa0.y);
        As2[arow][acg + 2] = tf32_split(pa0.z);
        As2[arow][acg + 3] = tf32_split(pa0.w);
        As2[arow][acg + 4] = tf32_split(pa1.x);
        As2[arow][acg + 5] = tf32_split(pa1.y);
        As2[arow][acg + 6] = tf32_split(pa1.z);
        As2[arow][acg + 7] = tf32_split(pa1.w);
        Ws2[wng + 0][wrow] = tf32_split(pw0.x);
        Ws2[wng + 1][wrow] = tf32_split(pw0.y);
        Ws2[wng + 2][wrow] = tf32_split(pw0.z);
        Ws2[wng + 3][wrow] = tf32_split(pw0.w);
        __syncthreads();

        if (k0 + GK < Kdim) {
            int kn = k0 + GK;
            pa0 = *(const float4*)(A + (size_t)(bm + arow) * Kdim + kn + acg);
            pa1 = *(const float4*)(A + (size_t)(bm + arow) * Kdim + kn + acg + 4);
            pw0 = *(const float4*)(W + (size_t)(kn + wrow) * Ndim + bn + wng);
        }

#pragma unroll
        for (int ks = 0; ks < 2; ks++) {
            const int kb = ks * 8;
            float2 aA[2][4];
#pragma unroll
            for (int mb = 0; mb < 2; mb++) {
                aA[mb][0] = As2[wm + mb * 16 + qr    ][kb + qc    ];
                aA[mb][1] = As2[wm + mb * 16 + qr + 8][kb + qc    ];
                aA[mb][2] = As2[wm + mb * 16 + qr    ][kb + qc + 4];
                aA[mb][3] = As2[wm + mb * 16 + qr + 8][kb + qc + 4];
            }
#pragma unroll
            for (int nb = 0; nb < 4; nb++) {
                float2 b0 = Ws2[wn + nb * 8 + qr][kb + qc    ];
                float2 b1 = Ws2[wn + nb * 8 + qr][kb + qc + 4];
#pragma unroll
                for (int mb = 0; mb < 2; mb++) {
                    // hi*hi
                    mma_tf32(c[mb][nb], aA[mb][0].x, aA[mb][1].x,
                             aA[mb][2].x, aA[mb][3].x, b0.x, b1.x);
                    // lo*hi
                    mma_tf32(c[mb][nb], aA[mb][0].y, aA[mb][1].y,
                             aA[mb][2].y, aA[mb][3].y, b0.x, b1.x);
                    // hi*lo
                    mma_tf32(c[mb][nb], aA[mb][0].x, aA[mb][1].x,
                             aA[mb][2].x, aA[mb][3].x, b0.y, b1.y);
                }
            }
        }
        __syncthreads();
    }

    // epilogue
#pragma unroll
    for (int nb = 0; nb < 4; nb++) {
        int n = bn + wn + nb * 8 + qc * 2;
        float2 bv = make_float2(0.f, 0.f);
        if (bias) bv = *(const float2*)(bias + n);
#pragma unroll
        for (int mb = 0; mb < 2; mb++) {
            int m = bm + wm + mb * 16 + qr;
            *(float2*)(C + (size_t)m * Ndim + n) =
                make_float2(c[mb][nb][0] + bv.x, c[mb][nb][1] + bv.y);
            *(float2*)(C + (size_t)(m + 8) * Ndim + n) =
                make_float2(c[mb][nb][2] + bv.x, c[mb][nb][3] + bv.y);
        }
    }
}

// ---------------------------------------------------------------------------
// Tensor-core flash attention (tf32 mma.sync, fp32 accumulate, exp2 softmax).
// Grid: (S/64, H, B), 128 threads = 4 warps -> 2-3 CTAs/SM (was 1).
// Warp w owns q rows [w*16, w*16+16), full 64-kv width: warp-local softmax,
// register-resident P (C-frag -> A-frag via quad shuffles).
// ---------------------------------------------------------------------------
#define BMQ 64
#define BNK 64
#define KST 84
#define VST 88

__global__ __launch_bounds__(128, 2) void flash_attn_tc()
{
    __shared__ float Ks[BNK * KST];
    __shared__ float Vs[BNK * VST];

    const int tid  = threadIdx.x;
    const int w    = tid >> 5;
    const int lane = tid & 31;
    const int qr   = lane >> 2;
    const int qc   = lane & 3;
    const int q0   = blockIdx.x * BMQ;
    const int h    = blockIdx.y;
    const int b    = blockIdx.z;

    const float QS = 0.11180339887498949f * 1.4426950408889634f; // scale*log2e

    const float* qg = g_q + (size_t)(b * S_ + q0 + w * 16) * D_ + h * DH_;
    const float* kg = g_k + (size_t)(b * S_) * D_ + h * DH_;
    const float* vg = g_v + (size_t)(b * S_) * D_ + h * DH_;

    float qa[10][4];
#pragma unroll
    for (int kb = 0; kb < 10; kb++) {
        qa[kb][0] = to_tf32(qg[(qr    ) * D_ + kb * 8 + qc    ] * QS);
        qa[kb][1] = to_tf32(qg[(qr + 8) * D_ + kb * 8 + qc    ] * QS);
        qa[kb][2] = to_tf32(qg[(qr    ) * D_ + kb * 8 + qc + 4] * QS);
        qa[kb][3] = to_tf32(qg[(qr + 8) * D_ + kb * 8 + qc + 4] * QS);
    }

    float m0 = -INFINITY, m1 = -INFINITY, l0 = 0.f, l1 = 0.f;
    float of[10][4];
#pragma unroll
    for (int n = 0; n < 10; n++)
#pragma unroll
        for (int r = 0; r < 4; r++) of[n][r] = 0.f;

    for (int t = 0; t < S_ / BNK; t++) {
        const int kv0 = t * BNK;
        __syncthreads();
        for (int idx = tid; idx < BNK * 20; idx += 128) {
            int r = idx / 20, c4 = (idx % 20) * 4;
            float4 k4 = *(const float4*)(kg + (size_t)(kv0 + r) * D_ + c4);
            float4 v4 = *(const float4*)(vg + (size_t)(kv0 + r) * D_ + c4);
            *(float4*)&Ks[r * KST + c4] = make_float4(
                to_tf32(k4.x), to_tf32(k4.y), to_tf32(k4.z), to_tf32(k4.w));
            *(float4*)&Vs[r * VST + c4] = make_float4(
                to_tf32(v4.x), to_tf32(v4.y), to_tf32(v4.z), to_tf32(v4.w));
        }
        __syncthreads();

        // ---- S = Q K^T ----
        float sf[8][4];
#pragma unroll
        for (int n = 0; n < 8; n++)
#pragma unroll
            for (int r = 0; r < 4; r++) sf[n][r] = 0.f;

#pragma unroll
        for (int kb = 0; kb < 10; kb++)
#pragma unroll
            for (int nb = 0; nb < 8; nb++) {
                float b0 = Ks[(nb * 8 + qr) * KST + kb * 8 + qc];
                float b1 = Ks[(nb * 8 + qr) * KST + kb * 8 + qc + 4];
                mma_tf32(sf[nb], qa[kb][0], qa[kb][1], qa[kb][2], qa[kb][3],
                         b0, b1);
            }

        // ---- online softmax (exp2 domain, quad-wide rows) ----
        float rmax0 = -INFINITY, rmax1 = -INFINITY;
#pragma unroll
        for (int nb = 0; nb < 8; nb++) {
            rmax0 = fmaxf(rmax0, fmaxf(sf[nb][0], sf[nb][1]));
            rmax1 = fmaxf(rmax1, fmaxf(sf[nb][2], sf[nb][3]));
        }
#pragma unroll
        for (int off = 1; off <= 2; off <<= 1) {
            rmax0 = fmaxf(rmax0, __shfl_xor_sync(0xffffffffu, rmax0, off));
            rmax1 = fmaxf(rmax1, __shfl_xor_sync(0xffffffffu, rmax1, off));
        }
        float mn0 = fmaxf(m0, rmax0), mn1 = fmaxf(m1, rmax1);
        float cr0 = ex2(m0 - mn0),    cr1 = ex2(m1 - mn1);
        m0 = mn0; m1 = mn1;

        float rs0 = 0.f, rs1 = 0.f;
#pragma unroll
        for (int nb = 0; nb < 8; nb++) {
            sf[nb][0] = ex2(sf[nb][0] - mn0); rs0 += sf[nb][0];
            sf[nb][1] = ex2(sf[nb][1] - mn0); rs0 += sf[nb][1];
            sf[nb][2] = ex2(sf[nb][2] - mn1); rs1 += sf[nb][2];
            sf[nb][3] = ex2(sf[nb][3] - mn1); rs1 += sf[nb][3];
        }
#pragma unroll
        for (int off = 1; off <= 2; off <<= 1) {
            rs0 += __shfl_xor_sync(0xffffffffu, rs0, off);
            rs1 += __shfl_xor_sync(0xffffffffu, rs1, off);
        }
        l0 = l0 * cr0 + rs0;
        l1 = l1 * cr1 + rs1;
#pragma unroll
        for (int n = 0; n < 10; n++) {
            of[n][0] *= cr0; of[n][1] *= cr0;
            of[n][2] *= cr1; of[n][3] *= cr1;
        }

#pragma unroll
        for (int nb = 0; nb < 8; nb++)
#pragma unroll
            for (int r = 0; r < 4; r++) sf[nb][r] = to_tf32(sf[nb][r]);

        // ---- O += P V (C-frag -> A-frag via quad shuffles) ----
        const int srcA = (lane & ~3) | (qc >> 1);
        const int srcB = srcA + 2;
        const bool odd = qc & 1;
#pragma unroll
        for (int kk = 0; kk < 8; kk++) {
            float t00 = __shfl_sync(0xffffffffu, sf[kk][0], srcA);
            float t01 = __shfl_sync(0xffffffffu, sf[kk][1], srcA);
            float t10 = __shfl_sync(0xffffffffu, sf[kk][2], srcA);
            float t11 = __shfl_sync(0xffffffffu, sf[kk][3], srcA);
            float t20 = __shfl_sync(0xffffffffu, sf[kk][0], srcB);
            float t21 = __shfl_sync(0xffffffffu, sf[kk][1], srcB);
            float t30 = __shfl_sync(0xffffffffu, sf[kk][2], srcB);
            float t31 = __shfl_sync(0xffffffffu, sf[kk][3], srcB);
            float a0 = odd ? t01 : t00;
            float a1 = odd ? t11 : t10;
            float a2 = odd ? t21 : t20;
            float a3 = odd ? t31 : t30;
#pragma unroll
            for (int nb2 = 0; nb2 < 10; nb2++) {
                float b0 = Vs[(kk * 8 + qc    ) * VST + nb2 * 8 + qr];
                float b1 = Vs[(kk * 8 + qc + 4) * VST + nb2 * 8 + qr];
                mma_tf32(of[nb2], a0, a1, a2, a3, b0, b1);
            }
        }
    }

    float inv0 = 1.0f / l0, inv1 = 1.0f / l1;
    float* og = g_attn + (size_t)(b * S_ + q0 + w * 16) * D_ + h * DH_;
#pragma unroll
    for (int nb2 = 0; nb2 < 10; nb2++) {
        int col = nb2 * 8 + qc * 2;
        *(float2*)(og + (qr    ) * D_ + col) =
            make_float2(of[nb2][0] * inv0, of[nb2][1] * inv0);
        *(float2*)(og + (qr + 8) * D_ + col) =
            make_float2(of[nb2][2] * inv1, of[nb2][3] * inv1);
    }
}

// ---------------------------------------------------------------------------
extern "C" void kernel_launch(void* const* d_in, const int* in_sizes, int n_in,
                              void* d_out, int out_size)
{
    const float* x   = (const float*)d_in[0];
    const float* enc = (const float*)d_in[1];
    const float* Wq  = (const float*)d_in[2];
    const float* Wk  = (const float*)d_in[3];
    const float* Wv  = (const float*)d_in[4];
    const float* Wo  = (const float*)d_in[5];
    const float* bo  = (const float*)d_in[6];
    float* out = (float*)d_out;

    float *qp, *kp, *vp, *ap;
    cudaGetSymbolAddress((void**)&qp, g_q);
    cudaGetSymbolAddress((void**)&kp, g_k);
    cudaGetSymbolAddress((void**)&vp, g_v);
    cudaGetSymbolAddress((void**)&ap, g_attn);

    dim3 gemm_grid(D_ / GN, M_ / GM);    // (10, 32)
    gemm_tf32_split<<<gemm_grid, 256>>>(x,   Wq, nullptr, qp, D_, D_);
    gemm_tf32_split<<<gemm_grid, 256>>>(enc, Wk, nullptr, kp, D_, D_);
    gemm_tf32_split<<<gemm_grid, 256>>>(enc, Wv, nullptr, vp, D_, D_);

    dim3 attn_grid(S_ / BMQ, H_, B_);    // (32, 8, 2)
    flash_attn_tc<<<attn_grid, 128>>>();

    gemm_tf32_split<<<gemm_grid, 256>>>(ap, Wo, bo, out, D_, D_);
}

// round 14
// speedup vs baseline: 1.6563x; 1.6563x over previous
#include <cuda_runtime.h>
#include <cuda_bf16.h>
#include <math.h>
#include <stdint.h>

// Problem constants
#define B_  2
#define S_  2048
#define D_  640        // = H_*DH_
#define H_  8
#define DH_ 80
#define M_  (B_*S_)    // 4096

// Scratch (device globals — no allocations allowed)
static __device__ float g_q[M_*D_];
static __device__ float g_k[M_*D_];
static __device__ float g_v[M_*D_];
static __device__ float g_attn[M_*D_];

// ---------------------------------------------------------------------------
// Tensor-core helpers
// ---------------------------------------------------------------------------
__device__ __forceinline__ float to_tf32(float x) {
    uint32_t u;
    asm("cvt.rna.tf32.f32 %0, %1;" : "=r"(u) : "f"(x));
    return __uint_as_float(u);
}

__device__ __forceinline__ float ex2(float x) {
    float r;
    asm("ex2.approx.ftz.f32 %0, %1;" : "=f"(r) : "f"(x));
    return r;
}

__device__ __forceinline__ void mma_tf32(float c[4],
    float a0, float a1, float a2, float a3, float b0, float b1)
{
    asm volatile(
        "mma.sync.aligned.m16n8k8.row.col.f32.tf32.tf32.f32 "
        "{%0,%1,%2,%3}, {%4,%5,%6,%7}, {%8,%9}, {%0,%1,%2,%3};"
        : "+f"(c[0]), "+f"(c[1]), "+f"(c[2]), "+f"(c[3])
        : "r"(__float_as_uint(a0)), "r"(__float_as_uint(a1)),
          "r"(__float_as_uint(a2)), "r"(__float_as_uint(a3)),
          "r"(__float_as_uint(b0)), "r"(__float_as_uint(b1)));
}

__device__ __forceinline__ void mma_bf16(float c[4],
    uint32_t a0, uint32_t a1, uint32_t a2, uint32_t a3,
    uint32_t b0, uint32_t b1)
{
    asm volatile(
        "mma.sync.aligned.m16n8k16.row.col.f32.bf16.bf16.f32 "
        "{%0,%1,%2,%3}, {%4,%5,%6,%7}, {%8,%9}, {%0,%1,%2,%3};"
        : "+f"(c[0]), "+f"(c[1]), "+f"(c[2]), "+f"(c[3])
        : "r"(a0), "r"(a1), "r"(a2), "r"(a3), "r"(b0), "r"(b1));
}

// Split (x0,x1) into bf16 hi/lo pairs, packed with even-k in the low half.
__device__ __forceinline__ void split2(float x0, float x1,
                                       uint32_t& hi, uint32_t& lo)
{
    float h0 = __bfloat162float(__float2bfloat16_rn(x0));
    float h1 = __bfloat162float(__float2bfloat16_rn(x1));
    __nv_bfloat162 h = __floats2bfloat162_rn(h0, h1);        // .x = low half
    __nv_bfloat162 l = __floats2bfloat162_rn(x0 - h0, x1 - h1);
    hi = *reinterpret_cast<uint32_t*>(&h);
    lo = *reinterpret_cast<uint32_t*>(&l);
}

// ---------------------------------------------------------------------------
// bf16-split GEMM (fp32-accurate: hi*hi + hi*lo + lo*hi; err ~2^-17).
// C[M,N] = A[M,K] @ W[K,N] (+bias). Tile 128x64x16, 256 threads = 8 warps,
// warp tile 32x32 (2 m-frags x 4 n-frags of m16n8k16).
// smem: separate hi/lo b32-packed arrays, pitch 12 b32 -> fragment LDS.32
// banks = 12*qr + qc (mod 32): fully conflict-free. B staged via n-coalesced
// gmem reads (no 8-way store conflicts).
// ---------------------------------------------------------------------------
#define GM 128
#define GN 64
#define GK 16
#define APB 12   // b32 pitch (8 k-pairs + 4 pad)
#define BPB 12

__global__ __launch_bounds__(256, 2) void gemm_bf16_split(
    const float* __restrict__ A, const float* __restrict__ W,
    const float* __restrict__ bias, float* __restrict__ C,
    int Kdim, int Ndim)
{
    __shared__ uint32_t Ahi[GM][APB], Alo[GM][APB];
    __shared__ uint32_t Bhi[GN][BPB], Blo[GN][BPB];

    const int tid  = threadIdx.x;
    const int w    = tid >> 5;
    const int lane = tid & 31;
    const int qr   = lane >> 2;
    const int qc   = lane & 3;
    const int wm   = (w & 3) * 32;
    const int wn   = (w >> 2) * 32;
    const int bm   = blockIdx.y * GM;
    const int bn   = blockIdx.x * GN;

    // A staging: 2 threads per row, each covers 8 consecutive k.
    const int arow  = tid >> 1;
    const int ahalf = tid & 1;
    // B staging: thread owns one n and 4 consecutive k (coalesced across lanes).
    const int nn = tid & 63;
    const int kg = tid >> 6;   // 0..3

    float c[2][4][4];
#pragma unroll
    for (int mb = 0; mb < 2; mb++)
#pragma unroll
        for (int nb = 0; nb < 4; nb++)
#pragma unroll
            for (int r = 0; r < 4; r++) c[mb][nb][r] = 0.f;

    // prefetch chunk 0
    float4 pa0 = *(const float4*)(A + (size_t)(bm + arow) * Kdim + ahalf * 8);
    float4 pa1 = *(const float4*)(A + (size_t)(bm + arow) * Kdim + ahalf * 8 + 4);
    float pb[4];
#pragma unroll
    for (int j = 0; j < 4; j++)
        pb[j] = W[(size_t)(kg * 4 + j) * Ndim + bn + nn];

    for (int k0 = 0; k0 < Kdim; k0 += GK) {
        // stage current chunk (hi/lo split), vectorized stores
        {
            uint32_t h[4], l[4];
            split2(pa0.x, pa0.y, h[0], l[0]);
            split2(pa0.z, pa0.w, h[1], l[1]);
            split2(pa1.x, pa1.y, h[2], l[2]);
            split2(pa1.z, pa1.w, h[3], l[3]);
            *(uint4*)&Ahi[arow][ahalf * 4] = make_uint4(h[0], h[1], h[2], h[3]);
            *(uint4*)&Alo[arow][ahalf * 4] = make_uint4(l[0], l[1], l[2], l[3]);

            uint32_t bh0, bl0, bh1, bl1;
            split2(pb[0], pb[1], bh0, bl0);
            split2(pb[2], pb[3], bh1, bl1);
            *(uint2*)&Bhi[nn][kg * 2] = make_uint2(bh0, bh1);
            *(uint2*)&Blo[nn][kg * 2] = make_uint2(bl0, bl1);
        }
        __syncthreads();

        if (k0 + GK < Kdim) {
            int kn = k0 + GK;
            pa0 = *(const float4*)(A + (size_t)(bm + arow) * Kdim + kn + ahalf * 8);
            pa1 = *(const float4*)(A + (size_t)(bm + arow) * Kdim + kn + ahalf * 8 + 4);
#pragma unroll
            for (int j = 0; j < 4; j++)
                pb[j] = W[(size_t)(kn + kg * 4 + j) * Ndim + bn + nn];
        }

        // fragments (all conflict-free LDS.32)
        uint32_t ah[2][4], al[2][4];
#pragma unroll
        for (int mb = 0; mb < 2; mb++) {
            int r = wm + mb * 16 + qr;
            ah[mb][0] = Ahi[r    ][qc    ];
            ah[mb][1] = Ahi[r + 8][qc    ];
            ah[mb][2] = Ahi[r    ][qc + 4];
            ah[mb][3] = Ahi[r + 8][qc + 4];
            al[mb][0] = Alo[r    ][qc    ];
            al[mb][1] = Alo[r + 8][qc    ];
            al[mb][2] = Alo[r    ][qc + 4];
            al[mb][3] = Alo[r + 8][qc + 4];
        }
#pragma unroll
        for (int nb = 0; nb < 4; nb++) {
            int n = wn + nb * 8 + qr;
            uint32_t bh0 = Bhi[n][qc], bh1 = Bhi[n][qc + 4];
            uint32_t bl0 = Blo[n][qc], bl1 = Blo[n][qc + 4];
#pragma unroll
            for (int mb = 0; mb < 2; mb++) {
                mma_bf16(c[mb][nb], ah[mb][0], ah[mb][1], ah[mb][2], ah[mb][3],
                         bh0, bh1);                                   // hi*hi
                mma_bf16(c[mb][nb], ah[mb][0], ah[mb][1], ah[mb][2], ah[mb][3],
                         bl0, bl1);                                   // hi*lo
                mma_bf16(c[mb][nb], al[mb][0], al[mb][1], al[mb][2], al[mb][3],
                         bh0, bh1);                                   // lo*hi
            }
        }
        __syncthreads();
    }

    // epilogue (same C-frag layout as m16n8k8)
#pragma unroll
    for (int nb = 0; nb < 4; nb++) {
        int n = bn + wn + nb * 8 + qc * 2;
        float2 bv = make_float2(0.f, 0.f);
        if (bias) bv = *(const float2*)(bias + n);
#pragma unroll
        for (int mb = 0; mb < 2; mb++) {
            int m = bm + wm + mb * 16 + qr;
            *(float2*)(C + (size_t)m * Ndim + n) =
                make_float2(c[mb][nb][0] + bv.x, c[mb][nb][1] + bv.y);
            *(float2*)(C + (size_t)(m + 8) * Ndim + n) =
                make_float2(c[mb][nb][2] + bv.x, c[mb][nb][3] + bv.y);
        }
    }
}

// ---------------------------------------------------------------------------
// Tensor-core flash attention (tf32 mma.sync, fp32 accumulate, exp2 softmax).
// Unchanged from R13 (250us, proven). Grid (S/64, H, B), 128 threads.
// ---------------------------------------------------------------------------
#define BMQ 64
#define BNK 64
#define KST 84
#define VST 88

__global__ __launch_bounds__(128, 2) void flash_attn_tc()
{
    __shared__ float Ks[BNK * KST];
    __shared__ float Vs[BNK * VST];

    const int tid  = threadIdx.x;
    const int w    = tid >> 5;
    const int lane = tid & 31;
    const int qr   = lane >> 2;
    const int qc   = lane & 3;
    const int q0   = blockIdx.x * BMQ;
    const int h    = blockIdx.y;
    const int b    = blockIdx.z;

    const float QS = 0.11180339887498949f * 1.4426950408889634f; // scale*log2e

    const float* qg = g_q + (size_t)(b * S_ + q0 + w * 16) * D_ + h * DH_;
    const float* kg = g_k + (size_t)(b * S_) * D_ + h * DH_;
    const float* vg = g_v + (size_t)(b * S_) * D_ + h * DH_;

    float qa[10][4];
#pragma unroll
    for (int kb = 0; kb < 10; kb++) {
        qa[kb][0] = to_tf32(qg[(qr    ) * D_ + kb * 8 + qc    ] * QS);
        qa[kb][1] = to_tf32(qg[(qr + 8) * D_ + kb * 8 + qc    ] * QS);
        qa[kb][2] = to_tf32(qg[(qr    ) * D_ + kb * 8 + qc + 4] * QS);
        qa[kb][3] = to_tf32(qg[(qr + 8) * D_ + kb * 8 + qc + 4] * QS);
    }

    float m0 = -INFINITY, m1 = -INFINITY, l0 = 0.f, l1 = 0.f;
    float of[10][4];
#pragma unroll
    for (int n = 0; n < 10; n++)
#pragma unroll
        for (int r = 0; r < 4; r++) of[n][r] = 0.f;

    for (int t = 0; t < S_ / BNK; t++) {
        const int kv0 = t * BNK;
        __syncthreads();
        for (int idx = tid; idx < BNK * 20; idx += 128) {
            int r = idx / 20, c4 = (idx % 20) * 4;
            float4 k4 = *(const float4*)(kg + (size_t)(kv0 + r) * D_ + c4);
            float4 v4 = *(const float4*)(vg + (size_t)(kv0 + r) * D_ + c4);
            *(float4*)&Ks[r * KST + c4] = make_float4(
                to_tf32(k4.x), to_tf32(k4.y), to_tf32(k4.z), to_tf32(k4.w));
            *(float4*)&Vs[r * VST + c4] = make_float4(
                to_tf32(v4.x), to_tf32(v4.y), to_tf32(v4.z), to_tf32(v4.w));
        }
        __syncthreads();

        // ---- S = Q K^T ----
        float sf[8][4];
#pragma unroll
        for (int n = 0; n < 8; n++)
#pragma unroll
            for (int r = 0; r < 4; r++) sf[n][r] = 0.f;

#pragma unroll
        for (int kb = 0; kb < 10; kb++)
#pragma unroll
            for (int nb = 0; nb < 8; nb++) {
                float b0 = Ks[(nb * 8 + qr) * KST + kb * 8 + qc];
                float b1 = Ks[(nb * 8 + qr) * KST + kb * 8 + qc + 4];
                mma_tf32(sf[nb], qa[kb][0], qa[kb][1], qa[kb][2], qa[kb][3],
                         b0, b1);
            }

        // ---- online softmax (exp2 domain, quad-wide rows) ----
        float rmax0 = -INFINITY, rmax1 = -INFINITY;
#pragma unroll
        for (int nb = 0; nb < 8; nb++) {
            rmax0 = fmaxf(rmax0, fmaxf(sf[nb][0], sf[nb][1]));
            rmax1 = fmaxf(rmax1, fmaxf(sf[nb][2], sf[nb][3]));
        }
#pragma unroll
        for (int off = 1; off <= 2; off <<= 1) {
            rmax0 = fmaxf(rmax0, __shfl_xor_sync(0xffffffffu, rmax0, off));
            rmax1 = fmaxf(rmax1, __shfl_xor_sync(0xffffffffu, rmax1, off));
        }
        float mn0 = fmaxf(m0, rmax0), mn1 = fmaxf(m1, rmax1);
        float cr0 = ex2(m0 - mn0),    cr1 = ex2(m1 - mn1);
        m0 = mn0; m1 = mn1;

        float rs0 = 0.f, rs1 = 0.f;
#pragma unroll
        for (int nb = 0; nb < 8; nb++) {
            sf[nb][0] = ex2(sf[nb][0] - mn0); rs0 += sf[nb][0];
            sf[nb][1] = ex2(sf[nb][1] - mn0); rs0 += sf[nb][1];
            sf[nb][2] = ex2(sf[nb][2] - mn1); rs1 += sf[nb][2];
            sf[nb][3] = ex2(sf[nb][3] - mn1); rs1 += sf[nb][3];
        }
#pragma unroll
        for (int off = 1; off <= 2; off <<= 1) {
            rs0 += __shfl_xor_sync(0xffffffffu, rs0, off);
            rs1 += __shfl_xor_sync(0xffffffffu, rs1, off);
        }
        l0 = l0 * cr0 + rs0;
        l1 = l1 * cr1 + rs1;
#pragma unroll
        for (int n = 0; n < 10; n++) {
            of[n][0] *= cr0; of[n][1] *= cr0;
            of[n][2] *= cr1; of[n][3] *= cr1;
        }

#pragma unroll
        for (int nb = 0; nb < 8; nb++)
#pragma unroll
            for (int r = 0; r < 4; r++) sf[nb][r] = to_tf32(sf[nb][r]);

        // ---- O += P V (C-frag -> A-frag via quad shuffles) ----
        const int srcA = (lane & ~3) | (qc >> 1);
        const int srcB = srcA + 2;
        const bool odd = qc & 1;
#pragma unroll
        for (int kk = 0; kk < 8; kk++) {
            float t00 = __shfl_sync(0xffffffffu, sf[kk][0], srcA);
            float t01 = __shfl_sync(0xffffffffu, sf[kk][1], srcA);
            float t10 = __shfl_sync(0xffffffffu, sf[kk][2], srcA);
            float t11 = __shfl_sync(0xffffffffu, sf[kk][3], srcA);
            float t20 = __shfl_sync(0xffffffffu, sf[kk][0], srcB);
            float t21 = __shfl_sync(0xffffffffu, sf[kk][1], srcB);
            float t30 = __shfl_sync(0xffffffffu, sf[kk][2], srcB);
            float t31 = __shfl_sync(0xffffffffu, sf[kk][3], srcB);
            float a0 = odd ? t01 : t00;
            float a1 = odd ? t11 : t10;
            float a2 = odd ? t21 : t20;
            float a3 = odd ? t31 : t30;
#pragma unroll
            for (int nb2 = 0; nb2 < 10; nb2++) {
                float b0 = Vs[(kk * 8 + qc    ) * VST + nb2 * 8 + qr];
                float b1 = Vs[(kk * 8 + qc + 4) * VST + nb2 * 8 + qr];
                mma_tf32(of[nb2], a0, a1, a2, a3, b0, b1);
            }
        }
    }

    float inv0 = 1.0f / l0, inv1 = 1.0f / l1;
    float* og = g_attn + (size_t)(b * S_ + q0 + w * 16) * D_ + h * DH_;
#pragma unroll
    for (int nb2 = 0; nb2 < 10; nb2++) {
        int col = nb2 * 8 + qc * 2;
        *(float2*)(og + (qr    ) * D_ + col) =
            make_float2(of[nb2][0] * inv0, of[nb2][1] * inv0);
        *(float2*)(og + (qr + 8) * D_ + col) =
            make_float2(of[nb2][2] * inv1, of[nb2][3] * inv1);
    }
}

// ---------------------------------------------------------------------------
extern "C" void kernel_launch(void* const* d_in, const int* in_sizes, int n_in,
                              void* d_out, int out_size)
{
    const float* x   = (const float*)d_in[0];
    const float* enc = (const float*)d_in[1];
    const float* Wq  = (const float*)d_in[2];
    const float* Wk  = (const float*)d_in[3];
    const float* Wv  = (const float*)d_in[4];
    const float* Wo  = (const float*)d_in[5];
    const float* bo  = (const float*)d_in[6];
    float* out = (float*)d_out;

    float *qp, *kp, *vp, *ap;
    cudaGetSymbolAddress((void**)&qp, g_q);
    cudaGetSymbolAddress((void**)&kp, g_k);
    cudaGetSymbolAddress((void**)&vp, g_v);
    cudaGetSymbolAddress((void**)&ap, g_attn);

    dim3 gemm_grid(D_ / GN, M_ / GM);    // (10, 32)
    gemm_bf16_split<<<gemm_grid, 256>>>(x,   Wq, nullptr, qp, D_, D_);
    gemm_bf16_split<<<gemm_grid, 256>>>(enc, Wk, nullptr, kp, D_, D_);
    gemm_bf16_split<<<gemm_grid, 256>>>(enc, Wv, nullptr, vp, D_, D_);

    dim3 attn_grid(S_ / BMQ, H_, B_);    // (32, 8, 2)
    flash_attn_tc<<<attn_grid, 128>>>();

    gemm_bf16_split<<<gemm_grid, 256>>>(ap, Wo, bo, out, D_, D_);
}

// round 15
// speedup vs baseline: 1.7927x; 1.0824x over previous
#include <cuda_runtime.h>
#include <cuda_bf16.h>
#include <math.h>
#include <stdint.h>

// Problem constants
#define B_  2
#define S_  2048
#define D_  640        // = H_*DH_
#define H_  8
#define DH_ 80
#define M_  (B_*S_)    // 4096

// Scratch (device globals — no allocations allowed)
static __device__ float g_q[M_*D_];
static __device__ float g_k[M_*D_];   // tf32-converted by GEMM epilogue
static __device__ float g_v[M_*D_];   // tf32-converted by GEMM epilogue
static __device__ float g_attn[M_*D_];

// ---------------------------------------------------------------------------
// Tensor-core + async-copy helpers
// ---------------------------------------------------------------------------
__device__ __forceinline__ float to_tf32(float x) {
    uint32_t u;
    asm("cvt.rna.tf32.f32 %0, %1;" : "=r"(u) : "f"(x));
    return __uint_as_float(u);
}

__device__ __forceinline__ float ex2(float x) {
    float r;
    asm("ex2.approx.ftz.f32 %0, %1;" : "=f"(r) : "f"(x));
    return r;
}

__device__ __forceinline__ void mma_tf32(float c[4],
    float a0, float a1, float a2, float a3, float b0, float b1)
{
    asm volatile(
        "mma.sync.aligned.m16n8k8.row.col.f32.tf32.tf32.f32 "
        "{%0,%1,%2,%3}, {%4,%5,%6,%7}, {%8,%9}, {%0,%1,%2,%3};"
        : "+f"(c[0]), "+f"(c[1]), "+f"(c[2]), "+f"(c[3])
        : "r"(__float_as_uint(a0)), "r"(__float_as_uint(a1)),
          "r"(__float_as_uint(a2)), "r"(__float_as_uint(a3)),
          "r"(__float_as_uint(b0)), "r"(__float_as_uint(b1)));
}

__device__ __forceinline__ void mma_bf16(float c[4],
    uint32_t a0, uint32_t a1, uint32_t a2, uint32_t a3,
    uint32_t b0, uint32_t b1)
{
    asm volatile(
        "mma.sync.aligned.m16n8k16.row.col.f32.bf16.bf16.f32 "
        "{%0,%1,%2,%3}, {%4,%5,%6,%7}, {%8,%9}, {%0,%1,%2,%3};"
        : "+f"(c[0]), "+f"(c[1]), "+f"(c[2]), "+f"(c[3])
        : "r"(a0), "r"(a1), "r"(a2), "r"(a3), "r"(b0), "r"(b1));
}

__device__ __forceinline__ void split2(float x0, float x1,
                                       uint32_t& hi, uint32_t& lo)
{
    float h0 = __bfloat162float(__float2bfloat16_rn(x0));
    float h1 = __bfloat162float(__float2bfloat16_rn(x1));
    __nv_bfloat162 h = __floats2bfloat162_rn(h0, h1);        // .x = low half
    __nv_bfloat162 l = __floats2bfloat162_rn(x0 - h0, x1 - h1);
    hi = *reinterpret_cast<uint32_t*>(&h);
    lo = *reinterpret_cast<uint32_t*>(&l);
}

__device__ __forceinline__ void cp_async16(uint32_t saddr, const void* gptr) {
    asm volatile("cp.async.cg.shared.global [%0], [%1], 16;\n"
                 :: "r"(saddr), "l"(gptr));
}
__device__ __forceinline__ void cp_commit() {
    asm volatile("cp.async.commit_group;\n");
}
template<int N>
__device__ __forceinline__ void cp_wait() {
    asm volatile("cp.async.wait_group %0;\n" :: "n"(N));
}

// ---------------------------------------------------------------------------
// bf16-split GEMM (fp32-accurate: hi*hi + hi*lo + lo*hi; err ~2^-17).
// Unchanged from R14 except epilogue cvt_out flag (pre-converts K/V to tf32
// so the attention kernel can cp.async them raw — bit-identical numerics).
// ---------------------------------------------------------------------------
#define GM 128
#define GN 64
#define GK 16
#define APB 12
#define BPB 12

__global__ __launch_bounds__(256, 2) void gemm_bf16_split(
    const float* __restrict__ A, const float* __restrict__ W,
    const float* __restrict__ bias, float* __restrict__ C,
    int Kdim, int Ndim, int cvt_out)
{
    __shared__ uint32_t Ahi[GM][APB], Alo[GM][APB];
    __shared__ uint32_t Bhi[GN][BPB], Blo[GN][BPB];

    const int tid  = threadIdx.x;
    const int w    = tid >> 5;
    const int lane = tid & 31;
    const int qr   = lane >> 2;
    const int qc   = lane & 3;
    const int wm   = (w & 3) * 32;
    const int wn   = (w >> 2) * 32;
    const int bm   = blockIdx.y * GM;
    const int bn   = blockIdx.x * GN;

    const int arow  = tid >> 1;
    const int ahalf = tid & 1;
    const int nn = tid & 63;
    const int kg = tid >> 6;

    float c[2][4][4];
#pragma unroll
    for (int mb = 0; mb < 2; mb++)
#pragma unroll
        for (int nb = 0; nb < 4; nb++)
#pragma unroll
            for (int r = 0; r < 4; r++) c[mb][nb][r] = 0.f;

    float4 pa0 = *(const float4*)(A + (size_t)(bm + arow) * Kdim + ahalf * 8);
    float4 pa1 = *(const float4*)(A + (size_t)(bm + arow) * Kdim + ahalf * 8 + 4);
    float pb[4];
#pragma unroll
    for (int j = 0; j < 4; j++)
        pb[j] = W[(size_t)(kg * 4 + j) * Ndim + bn + nn];

    for (int k0 = 0; k0 < Kdim; k0 += GK) {
        {
            uint32_t h[4], l[4];
            split2(pa0.x, pa0.y, h[0], l[0]);
            split2(pa0.z, pa0.w, h[1], l[1]);
            split2(pa1.x, pa1.y, h[2], l[2]);
            split2(pa1.z, pa1.w, h[3], l[3]);
            *(uint4*)&Ahi[arow][ahalf * 4] = make_uint4(h[0], h[1], h[2], h[3]);
            *(uint4*)&Alo[arow][ahalf * 4] = make_uint4(l[0], l[1], l[2], l[3]);

            uint32_t bh0, bl0, bh1, bl1;
            split2(pb[0], pb[1], bh0, bl0);
            split2(pb[2], pb[3], bh1, bl1);
            *(uint2*)&Bhi[nn][kg * 2] = make_uint2(bh0, bh1);
            *(uint2*)&Blo[nn][kg * 2] = make_uint2(bl0, bl1);
        }
        __syncthreads();

        if (k0 + GK < Kdim) {
            int kn = k0 + GK;
            pa0 = *(const float4*)(A + (size_t)(bm + arow) * Kdim + kn + ahalf * 8);
            pa1 = *(const float4*)(A + (size_t)(bm + arow) * Kdim + kn + ahalf * 8 + 4);
#pragma unroll
            for (int j = 0; j < 4; j++)
                pb[j] = W[(size_t)(kn + kg * 4 + j) * Ndim + bn + nn];
        }

        uint32_t ah[2][4], al[2][4];
#pragma unroll
        for (int mb = 0; mb < 2; mb++) {
            int r = wm + mb * 16 + qr;
            ah[mb][0] = Ahi[r    ][qc    ];
            ah[mb][1] = Ahi[r + 8][qc    ];
            ah[mb][2] = Ahi[r    ][qc + 4];
            ah[mb][3] = Ahi[r + 8][qc + 4];
            al[mb][0] = Alo[r    ][qc    ];
            al[mb][1] = Alo[r + 8][qc    ];
            al[mb][2] = Alo[r    ][qc + 4];
            al[mb][3] = Alo[r + 8][qc + 4];
        }
#pragma unroll
        for (int nb = 0; nb < 4; nb++) {
            int n = wn + nb * 8 + qr;
            uint32_t bh0 = Bhi[n][qc], bh1 = Bhi[n][qc + 4];
            uint32_t bl0 = Blo[n][qc], bl1 = Blo[n][qc + 4];
#pragma unroll
            for (int mb = 0; mb < 2; mb++) {
                mma_bf16(c[mb][nb], ah[mb][0], ah[mb][1], ah[mb][2], ah[mb][3],
                         bh0, bh1);
                mma_bf16(c[mb][nb], ah[mb][0], ah[mb][1], ah[mb][2], ah[mb][3],
                         bl0, bl1);
                mma_bf16(c[mb][nb], al[mb][0], al[mb][1], al[mb][2], al[mb][3],
                         bh0, bh1);
            }
        }
        __syncthreads();
    }

#pragma unroll
    for (int nb = 0; nb < 4; nb++) {
        int n = bn + wn + nb * 8 + qc * 2;
        float2 bv = make_float2(0.f, 0.f);
        if (bias) bv = *(const float2*)(bias + n);
#pragma unroll
        for (int mb = 0; mb < 2; mb++) {
            int m = bm + wm + mb * 16 + qr;
            float2 v0 = make_float2(c[mb][nb][0] + bv.x, c[mb][nb][1] + bv.y);
            float2 v1 = make_float2(c[mb][nb][2] + bv.x, c[mb][nb][3] + bv.y);
            if (cvt_out) {
                v0.x = to_tf32(v0.x); v0.y = to_tf32(v0.y);
                v1.x = to_tf32(v1.x); v1.y = to_tf32(v1.y);
            }
            *(float2*)(C + (size_t)m * Ndim + n) = v0;
            *(float2*)(C + (size_t)(m + 8) * Ndim + n) = v1;
        }
    }
}

// ---------------------------------------------------------------------------
// Tensor-core flash attention (tf32 mma.sync, fp32 acc, exp2 softmax).
// K/V arrive pre-converted to tf32 -> raw cp.async into a 2-stage double
// buffer; tile t+1 loads overlap tile t compute. Grid (S/64,H,B), 128 thr.
// ---------------------------------------------------------------------------
#define BMQ 64
#define BNK 64
#define KST 84
#define VST 88
#define KBUF (BNK*KST)
#define VBUF (BNK*VST)
#define ATTN_SMEM ((2*KBUF + 2*VBUF) * 4)   // 88064 bytes

__global__ __launch_bounds__(128, 2) void flash_attn_tc()
{
    extern __shared__ float smdyn[];
    float* KsB = smdyn;              // [2][KBUF]
    float* VsB = smdyn + 2 * KBUF;   // [2][VBUF]

    const int tid  = threadIdx.x;
    const int w    = tid >> 5;
    const int lane = tid & 31;
    const int qr   = lane >> 2;
    const int qc   = lane & 3;
    const int q0   = blockIdx.x * BMQ;
    const int h    = blockIdx.y;
    const int b    = blockIdx.z;

    const float QS = 0.11180339887498949f * 1.4426950408889634f; // scale*log2e

    const float* qg = g_q + (size_t)(b * S_ + q0 + w * 16) * D_ + h * DH_;
    const float* kg = g_k + (size_t)(b * S_) * D_ + h * DH_;
    const float* vg = g_v + (size_t)(b * S_) * D_ + h * DH_;

    // Per-thread cp.async slots: 10 (row, col4) pairs covering 64x20 float4.
    const int r0_ = (tid * 10) / 20 * 0;  // (silence unused-warning pattern)
    (void)r0_;

    uint32_t ks_s[2], vs_s[2];
    ks_s[0] = (uint32_t)__cvta_generic_to_shared(KsB);
    ks_s[1] = (uint32_t)__cvta_generic_to_shared(KsB + KBUF);
    vs_s[0] = (uint32_t)__cvta_generic_to_shared(VsB);
    vs_s[1] = (uint32_t)__cvta_generic_to_shared(VsB + VBUF);

    // Q fragments (tf32, scale folded) — resident for the whole kernel.
    float qa[10][4];
#pragma unroll
    for (int kb = 0; kb < 10; kb++) {
        qa[kb][0] = to_tf32(qg[(qr    ) * D_ + kb * 8 + qc    ] * QS);
        qa[kb][1] = to_tf32(qg[(qr + 8) * D_ + kb * 8 + qc    ] * QS);
        qa[kb][2] = to_tf32(qg[(qr    ) * D_ + kb * 8 + qc + 4] * QS);
        qa[kb][3] = to_tf32(qg[(qr + 8) * D_ + kb * 8 + qc + 4] * QS);
    }

    float m0 = -INFINITY, m1 = -INFINITY, l0 = 0.f, l1 = 0.f;
    float of[10][4];
#pragma unroll
    for (int n = 0; n < 10; n++)
#pragma unroll
        for (int r = 0; r < 4; r++) of[n][r] = 0.f;

    // ---- async tile loader: 10 K + 10 V cp.async.16 per thread ----
    auto load_tile = [&](int t, int buf) {
        const int kv0 = t * BNK;
#pragma unroll
        for (int i = 0; i < 10; i++) {
            int idx = tid + i * 128;
            int r = idx / 20, c4 = (idx % 20) * 4;
            cp_async16(ks_s[buf] + (uint32_t)(r * KST + c4) * 4,
                       kg + (size_t)(kv0 + r) * D_ + c4);
            cp_async16(vs_s[buf] + (uint32_t)(r * VST + c4) * 4,
                       vg + (size_t)(kv0 + r) * D_ + c4);
        }
        cp_commit();
    };

    load_tile(0, 0);   // prologue

    const int NT = S_ / BNK;
    for (int t = 0; t < NT; t++) {
        const int buf = t & 1;
        if (t + 1 < NT) {
            load_tile(t + 1, buf ^ 1);
            cp_wait<1>();          // tile t complete, t+1 in flight
        } else {
            cp_wait<0>();
        }
        __syncthreads();

        const float* Ks = KsB + buf * KBUF;
        const float* Vs = VsB + buf * VBUF;

        // ---- S = Q K^T ----
        float sf[8][4];
#pragma unroll
        for (int n = 0; n < 8; n++)
#pragma unroll
            for (int r = 0; r < 4; r++) sf[n][r] = 0.f;

#pragma unroll
        for (int kb = 0; kb < 10; kb++)
#pragma unroll
            for (int nb = 0; nb < 8; nb++) {
                float b0 = Ks[(nb * 8 + qr) * KST + kb * 8 + qc];
                float b1 = Ks[(nb * 8 + qr) * KST + kb * 8 + qc + 4];
                mma_tf32(sf[nb], qa[kb][0], qa[kb][1], qa[kb][2], qa[kb][3],
                         b0, b1);
            }

        // ---- online softmax (exp2 domain, quad-wide rows) ----
        float rmax0 = -INFINITY, rmax1 = -INFINITY;
#pragma unroll
        for (int nb = 0; nb < 8; nb++) {
            rmax0 = fmaxf(rmax0, fmaxf(sf[nb][0], sf[nb][1]));
            rmax1 = fmaxf(rmax1, fmaxf(sf[nb][2], sf[nb][3]));
        }
#pragma unroll
        for (int off = 1; off <= 2; off <<= 1) {
            rmax0 = fmaxf(rmax0, __shfl_xor_sync(0xffffffffu, rmax0, off));
            rmax1 = fmaxf(rmax1, __shfl_xor_sync(0xffffffffu, rmax1, off));
        }
        float mn0 = fmaxf(m0, rmax0), mn1 = fmaxf(m1, rmax1);
        float cr0 = ex2(m0 - mn0),    cr1 = ex2(m1 - mn1);
        m0 = mn0; m1 = mn1;

        float rs0 = 0.f, rs1 = 0.f;
#pragma unroll
        for (int nb = 0; nb < 8; nb++) {
            sf[nb][0] = ex2(sf[nb][0] - mn0); rs0 += sf[nb][0];
            sf[nb][1] = ex2(sf[nb][1] - mn0); rs0 += sf[nb][1];
            sf[nb][2] = ex2(sf[nb][2] - mn1); rs1 += sf[nb][2];
            sf[nb][3] = ex2(sf[nb][3] - mn1); rs1 += sf[nb][3];
        }
#pragma unroll
        for (int off = 1; off <= 2; off <<= 1) {
            rs0 += __shfl_xor_sync(0xffffffffu, rs0, off);
            rs1 += __shfl_xor_sync(0xffffffffu, rs1, off);
        }
        l0 = l0 * cr0 + rs0;
        l1 = l1 * cr1 + rs1;
#pragma unroll
        for (int n = 0; n < 10; n++) {
            of[n][0] *= cr0; of[n][1] *= cr0;
            of[n][2] *= cr1; of[n][3] *= cr1;
        }

#pragma unroll
        for (int nb = 0; nb < 8; nb++)
#pragma unroll
            for (int r = 0; r < 4; r++) sf[nb][r] = to_tf32(sf[nb][r]);

        // ---- O += P V (C-frag -> A-frag via quad shuffles) ----
        const int srcA = (lane & ~3) | (qc >> 1);
        const int srcB = srcA + 2;
        const bool odd = qc & 1;
#pragma unroll
        for (int kk = 0; kk < 8; kk++) {
            float t00 = __shfl_sync(0xffffffffu, sf[kk][0], srcA);
            float t01 = __shfl_sync(0xffffffffu, sf[kk][1], srcA);
            float t10 = __shfl_sync(0xffffffffu, sf[kk][2], srcA);
            float t11 = __shfl_sync(0xffffffffu, sf[kk][3], srcA);
            float t20 = __shfl_sync(0xffffffffu, sf[kk][0], srcB);
            float t21 = __shfl_sync(0xffffffffu, sf[kk][1], srcB);
            float t30 = __shfl_sync(0xffffffffu, sf[kk][2], srcB);
            float t31 = __shfl_sync(0xffffffffu, sf[kk][3], srcB);
            float a0 = odd ? t01 : t00;
            float a1 = odd ? t11 : t10;
            float a2 = odd ? t21 : t20;
            float a3 = odd ? t31 : t30;
#pragma unroll
            for (int nb2 = 0; nb2 < 10; nb2++) {
                float b0 = Vs[(kk * 8 + qc    ) * VST + nb2 * 8 + qr];
                float b1 = Vs[(kk * 8 + qc + 4) * VST + nb2 * 8 + qr];
                mma_tf32(of[nb2], a0, a1, a2, a3, b0, b1);
            }
        }
        __syncthreads();   // all warps done with this buffer before its reuse
    }

    float inv0 = 1.0f / l0, inv1 = 1.0f / l1;
    float* og = g_attn + (size_t)(b * S_ + q0 + w * 16) * D_ + h * DH_;
#pragma unroll
    for (int nb2 = 0; nb2 < 10; nb2++) {
        int col = nb2 * 8 + qc * 2;
        *(float2*)(og + (qr    ) * D_ + col) =
            make_float2(of[nb2][0] * inv0, of[nb2][1] * inv0);
        *(float2*)(og + (qr + 8) * D_ + col) =
            make_float2(of[nb2][2] * inv1, of[nb2][3] * inv1);
    }
}

// ---------------------------------------------------------------------------
extern "C" void kernel_launch(void* const* d_in, const int* in_sizes, int n_in,
                              void* d_out, int out_size)
{
    const float* x   = (const float*)d_in[0];
    const float* enc = (const float*)d_in[1];
    const float* Wq  = (const float*)d_in[2];
    const float* Wk  = (const float*)d_in[3];
    const float* Wv  = (const float*)d_in[4];
    const float* Wo  = (const float*)d_in[5];
    const float* bo  = (const float*)d_in[6];
    float* out = (float*)d_out;

    float *qp, *kp, *vp, *ap;
    cudaGetSymbolAddress((void**)&qp, g_q);
    cudaGetSymbolAddress((void**)&kp, g_k);
    cudaGetSymbolAddress((void**)&vp, g_v);
    cudaGetSymbolAddress((void**)&ap, g_attn);

    cudaFuncSetAttribute(flash_attn_tc,
                         cudaFuncAttributeMaxDynamicSharedMemorySize,
                         ATTN_SMEM);

    dim3 gemm_grid(D_ / GN, M_ / GM);    // (10, 32)
    gemm_bf16_split<<<gemm_grid, 256>>>(x,   Wq, nullptr, qp, D_, D_, 0);
    gemm_bf16_split<<<gemm_grid, 256>>>(enc, Wk, nullptr, kp, D_, D_, 1);
    gemm_bf16_split<<<gemm_grid, 256>>>(enc, Wv, nullptr, vp, D_, D_, 1);

    dim3 attn_grid(S_ / BMQ, H_, B_);    // (32, 8, 2)
    flash_attn_tc<<<attn_grid, 128, ATTN_SMEM>>>();

    gemm_bf16_split<<<gemm_grid, 256>>>(ap, Wo, bo, out, D_, D_, 0);
}

// round 17
// speedup vs baseline: 2.1070x; 1.1753x over previous
#include <cuda_runtime.h>
#include <cuda_bf16.h>
#include <math.h>
#include <stdint.h>

// Problem constants
#define B_  2
#define S_  2048
#define D_  640        // = H_*DH_
#define H_  8
#define DH_ 80
#define M_  (B_*S_)    // 4096

// Scratch (device globals — no allocations allowed)
static __device__ float g_q[M_*D_];
static __device__ float g_k[M_*D_];   // tf32-converted by GEMM epilogue
static __device__ float g_v[M_*D_];   // tf32-converted by GEMM epilogue
static __device__ float g_attn[M_*D_];

// bf16 hi/lo split scratch (activations + transposed weights)
static __device__ __nv_bfloat16 g_xh[M_*D_], g_xl[M_*D_];   // x
static __device__ __nv_bfloat16 g_eh[M_*D_], g_el[M_*D_];   // encoder
static __device__ __nv_bfloat16 g_th[M_*D_], g_tl[M_*D_];   // attn out
static __device__ __nv_bfloat16 g_wh[4*D_*D_], g_wl[4*D_*D_]; // W^T x4

// ---------------------------------------------------------------------------
// Helpers (mma.sync only — tcgen05 PTX is rejected by this toolchain's
// sm_103 ptxas pass; confirmed R16)
// ---------------------------------------------------------------------------
__device__ __forceinline__ float to_tf32(float x) {
    uint32_t u;
    asm("cvt.rna.tf32.f32 %0, %1;" : "=r"(u) : "f"(x));
    return __uint_as_float(u);
}
__device__ __forceinline__ float ex2(float x) {
    float r;
    asm("ex2.approx.ftz.f32 %0, %1;" : "=f"(r) : "f"(x));
    return r;
}
__device__ __forceinline__ void mma_tf32(float c[4],
    float a0, float a1, float a2, float a3, float b0, float b1)
{
    asm volatile(
        "mma.sync.aligned.m16n8k8.row.col.f32.tf32.tf32.f32 "
        "{%0,%1,%2,%3}, {%4,%5,%6,%7}, {%8,%9}, {%0,%1,%2,%3};"
        : "+f"(c[0]), "+f"(c[1]), "+f"(c[2]), "+f"(c[3])
        : "r"(__float_as_uint(a0)), "r"(__float_as_uint(a1)),
          "r"(__float_as_uint(a2)), "r"(__float_as_uint(a3)),
          "r"(__float_as_uint(b0)), "r"(__float_as_uint(b1)));
}
__device__ __forceinline__ void mma_bf16(float c[4],
    uint32_t a0, uint32_t a1, uint32_t a2, uint32_t a3,
    uint32_t b0, uint32_t b1)
{
    asm volatile(
        "mma.sync.aligned.m16n8k16.row.col.f32.bf16.bf16.f32 "
        "{%0,%1,%2,%3}, {%4,%5,%6,%7}, {%8,%9}, {%0,%1,%2,%3};"
        : "+f"(c[0]), "+f"(c[1]), "+f"(c[2]), "+f"(c[3])
        : "r"(a0), "r"(a1), "r"(a2), "r"(a3), "r"(b0), "r"(b1));
}
// Split (x0,x1) into packed bf16 hi/lo (x0 in low half = array order).
__device__ __forceinline__ void split2(float x0, float x1,
                                       uint32_t& hi, uint32_t& lo)
{
    float h0 = __bfloat162float(__float2bfloat16_rn(x0));
    float h1 = __bfloat162float(__float2bfloat16_rn(x1));
    __nv_bfloat162 h = __floats2bfloat162_rn(h0, h1);
    __nv_bfloat162 l = __floats2bfloat162_rn(x0 - h0, x1 - h1);
    hi = *reinterpret_cast<uint32_t*>(&h);
    lo = *reinterpret_cast<uint32_t*>(&l);
}
__device__ __forceinline__ void cp_async16(uint32_t saddr, const void* gptr) {
    asm volatile("cp.async.cg.shared.global [%0], [%1], 16;\n"
                 :: "r"(saddr), "l"(gptr));
}
__device__ __forceinline__ void cp_commit() {
    asm volatile("cp.async.commit_group;\n");
}
template<int N>
__device__ __forceinline__ void cp_wait() {
    asm volatile("cp.async.wait_group %0;\n" :: "n"(N));
}
__device__ __forceinline__ uint32_t smem_u32(const void* p) {
    return (uint32_t)__cvta_generic_to_shared(p);
}

// ---------------------------------------------------------------------------
// Split pass kernels
// ---------------------------------------------------------------------------
__global__ __launch_bounds__(256) void asplit_kernel(
    const float* __restrict__ src,
    __nv_bfloat16* __restrict__ hi, __nv_bfloat16* __restrict__ lo)
{
    size_t i = ((size_t)blockIdx.x * 256 + threadIdx.x) * 4;
    float4 v = *(const float4*)(src + i);
    uint32_t h01, l01, h23, l23;
    split2(v.x, v.y, h01, l01);
    split2(v.z, v.w, h23, l23);
    *(uint2*)(hi + i) = make_uint2(h01, h23);
    *(uint2*)(lo + i) = make_uint2(l01, l23);
}

// Transpose-split: W[K,N] fp32 -> WT[N,K] bf16 hi/lo. Grid (20,20,4), blk (32,8).
__global__ __launch_bounds__(256) void wsplit_kernel(
    const float* __restrict__ W0, const float* __restrict__ W1,
    const float* __restrict__ W2, const float* __restrict__ W3,
    __nv_bfloat16* __restrict__ hi, __nv_bfloat16* __restrict__ lo)
{
    const float* W = (blockIdx.z == 0) ? W0 : (blockIdx.z == 1) ? W1
                   : (blockIdx.z == 2) ? W2 : W3;
    __nv_bfloat16* h = hi + (size_t)blockIdx.z * D_ * D_;
    __nv_bfloat16* l = lo + (size_t)blockIdx.z * D_ * D_;

    __shared__ float t[32][33];
    int n0 = blockIdx.x * 32, k0 = blockIdx.y * 32;
    int tx = threadIdx.x, ty = threadIdx.y;
#pragma unroll
    for (int j = 0; j < 4; j++) {
        int k = ty + j * 8;
        t[k][tx] = W[(size_t)(k0 + k) * D_ + n0 + tx];
    }
    __syncthreads();
#pragma unroll
    for (int j = 0; j < 4; j++) {
        int n = ty + j * 8;
        float v = t[tx][n];   // = W[k0+tx][n0+n]
        __nv_bfloat16 hh = __float2bfloat16_rn(v);
        h[(size_t)(n0 + n) * D_ + k0 + tx] = hh;
        l[(size_t)(n0 + n) * D_ + k0 + tx] =
            __float2bfloat16_rn(v - __bfloat162float(hh));
    }
}

// ---------------------------------------------------------------------------
// bf16-split GEMM, pre-split inputs, cp.async double-buffered.
// C[M,N] = A @ WT^T (+bias). Tile 128x64, K chunk 32, 256 thr = 8 warps,
// warp tile 32x32 (2 m-frags x 4 n-frags of m16n8k16), 3-term hi/lo.
// smem rows pitch 20 u32 (16 data + 4 pad): fragment banks 20*qr+qc+const
// hit all 32 banks (conflict-free); 16B-aligned for cp.async.
// ---------------------------------------------------------------------------
#define GM 128
#define GN 64
#define GK 32
#define APW 20                    // u32 pitch per row
#define A_U32 (GM*APW)            // 2560
#define B_U32 (GN*APW)            // 1280
#define STG_U32 (2*A_U32 + 2*B_U32)   // 7680 u32 = 30KB/stage
#define GEMM_SMEM (2*STG_U32*4)       // 61440 bytes

__global__ __launch_bounds__(256) void gemm_bf16_pre(
    const __nv_bfloat16* __restrict__ Ah, const __nv_bfloat16* __restrict__ Al,
    const __nv_bfloat16* __restrict__ Bh, const __nv_bfloat16* __restrict__ Bl,
    const float* __restrict__ bias, float* __restrict__ C, int cvt_out)
{
    extern __shared__ uint32_t smg[];

    const int tid  = threadIdx.x;
    const int w    = tid >> 5;
    const int lane = tid & 31;
    const int qr   = lane >> 2;
    const int qc   = lane & 3;
    const int wm   = (w & 3) * 32;
    const int wn   = (w >> 2) * 32;
    const int bm   = blockIdx.y * GM;
    const int bn   = blockIdx.x * GN;

    uint32_t sbase[2];
    sbase[0] = smem_u32(smg);
    sbase[1] = sbase[0] + STG_U32 * 4;
    // sub-array byte offsets within a stage
    const uint32_t oAh = 0, oAl = A_U32 * 4;
    const uint32_t oBh = 2 * A_U32 * 4, oBl = oBh + B_U32 * 4;

    float c[2][4][4];
#pragma unroll
    for (int mb = 0; mb < 2; mb++)
#pragma unroll
        for (int nb = 0; nb < 4; nb++)
#pragma unroll
            for (int r = 0; r < 4; r++) c[mb][nb][r] = 0.f;

    // ---- cp.async stage of one K-chunk (32 k) into buffer `buf` ----
    auto load_chunk = [&](int k0, int buf) {
        const uint32_t sb = sbase[buf];
        // A: 128 rows x 4 16B-chunks, hi+lo  (2 iters x 256 thr)
#pragma unroll
        for (int it = 0; it < 2; it++) {
            int i = tid + it * 256;
            int row = i >> 2, c4 = i & 3;
            uint32_t dst = (uint32_t)(row * APW + c4 * 4) * 4;
            size_t g = (size_t)(bm + row) * D_ + k0 + c4 * 8;
            cp_async16(sb + oAh + dst, Ah + g);
            cp_async16(sb + oAl + dst, Al + g);
        }
        // B: 64 rows x 4 chunks, hi+lo (1 iter)
        {
            int row = tid >> 2, c4 = tid & 3;
            uint32_t dst = (uint32_t)(row * APW + c4 * 4) * 4;
            size_t g = (size_t)(bn + row) * D_ + k0 + c4 * 8;
            cp_async16(sb + oBh + dst, Bh + g);
            cp_async16(sb + oBl + dst, Bl + g);
        }
        cp_commit();
    };

    load_chunk(0, 0);

    const int NCH = D_ / GK;   // 20
    for (int ch = 0; ch < NCH; ch++) {
        const int buf = ch & 1;
        if (ch + 1 < NCH) {
            load_chunk((ch + 1) * GK, buf ^ 1);
            cp_wait<1>();
        } else {
            cp_wait<0>();
        }
        __syncthreads();

        const uint32_t* Ahi = smg + (buf ? STG_U32 : 0);
        const uint32_t* Alo = Ahi + A_U32;
        const uint32_t* Bhi = Ahi + 2 * A_U32;
        const uint32_t* Blo = Bhi + B_U32;

#pragma unroll
        for (int ks = 0; ks < 2; ks++) {
            const int kp = ks * 8;   // k-pair offset within chunk
            uint32_t ah[2][4], al[2][4];
#pragma unroll
            for (int mb = 0; mb < 2; mb++) {
                int r = wm + mb * 16 + qr;
                ah[mb][0] = Ahi[r * APW + kp + qc];
                ah[mb][1] = Ahi[(r + 8) * APW + kp + qc];
                ah[mb][2] = Ahi[r * APW + kp + qc + 4];
                ah[mb][3] = Ahi[(r + 8) * APW + kp + qc + 4];
                al[mb][0] = Alo[r * APW + kp + qc];
                al[mb][1] = Alo[(r + 8) * APW + kp + qc];
                al[mb][2] = Alo[r * APW + kp + qc + 4];
                al[mb][3] = Alo[(r + 8) * APW + kp + qc + 4];
            }
#pragma unroll
            for (int nb = 0; nb < 4; nb++) {
                int n = wn + nb * 8 + qr;
                uint32_t bh0 = Bhi[n * APW + kp + qc];
                uint32_t bh1 = Bhi[n * APW + kp + qc + 4];
                uint32_t bl0 = Blo[n * APW + kp + qc];
                uint32_t bl1 = Blo[n * APW + kp + qc + 4];
#pragma unroll
                for (int mb = 0; mb < 2; mb++) {
                    mma_bf16(c[mb][nb], ah[mb][0], ah[mb][1],
                             ah[mb][2], ah[mb][3], bh0, bh1);   // hi*hi
                    mma_bf16(c[mb][nb], ah[mb][0], ah[mb][1],
                             ah[mb][2], ah[mb][3], bl0, bl1);   // hi*lo
                    mma_bf16(c[mb][nb], al[mb][0], al[mb][1],
                             al[mb][2], al[mb][3], bh0, bh1);   // lo*hi
                }
            }
        }
        __syncthreads();
    }

    // epilogue
#pragma unroll
    for (int nb = 0; nb < 4; nb++) {
        int n = bn + wn + nb * 8 + qc * 2;
        float2 bv = make_float2(0.f, 0.f);
        if (bias) bv = *(const float2*)(bias + n);
#pragma unroll
        for (int mb = 0; mb < 2; mb++) {
            int m = bm + wm + mb * 16 + qr;
            float2 v0 = make_float2(c[mb][nb][0] + bv.x, c[mb][nb][1] + bv.y);
            float2 v1 = make_float2(c[mb][nb][2] + bv.x, c[mb][nb][3] + bv.y);
            if (cvt_out) {
                v0.x = to_tf32(v0.x); v0.y = to_tf32(v0.y);
                v1.x = to_tf32(v1.x); v1.y = to_tf32(v1.y);
            }
            *(float2*)(C + (size_t)m * D_ + n) = v0;
            *(float2*)(C + (size_t)(m + 8) * D_ + n) = v1;
        }
    }
}

// ---------------------------------------------------------------------------
// Tensor-core flash attention (tf32 mma.sync) — unchanged from R15 (178us).
// ---------------------------------------------------------------------------
#define BMQ 64
#define BNK 64
#define KST 84
#define VST 88
#define KBUF (BNK*KST)
#define VBUF (BNK*VST)
#define ATTN_SMEM ((2*KBUF + 2*VBUF) * 4)

__global__ __launch_bounds__(128, 2) void flash_attn_tc()
{
    extern __shared__ float smdyn[];
    float* KsB = smdyn;
    float* VsB = smdyn + 2 * KBUF;

    const int tid  = threadIdx.x;
    const int w    = tid >> 5;
    const int lane = tid & 31;
    const int qr   = lane >> 2;
    const int qc   = lane & 3;
    const int q0   = blockIdx.x * BMQ;
    const int h    = blockIdx.y;
    const int b    = blockIdx.z;

    const float QS = 0.11180339887498949f * 1.4426950408889634f;

    const float* qg = g_q + (size_t)(b * S_ + q0 + w * 16) * D_ + h * DH_;
    const float* kg = g_k + (size_t)(b * S_) * D_ + h * DH_;
    const float* vg = g_v + (size_t)(b * S_) * D_ + h * DH_;

    uint32_t ks_s[2], vs_s[2];
    ks_s[0] = smem_u32(KsB);
    ks_s[1] = smem_u32(KsB + KBUF);
    vs_s[0] = smem_u32(VsB);
    vs_s[1] = smem_u32(VsB + VBUF);

    float qa[10][4];
#pragma unroll
    for (int kb = 0; kb < 10; kb++) {
        qa[kb][0] = to_tf32(qg[(qr    ) * D_ + kb * 8 + qc    ] * QS);
        qa[kb][1] = to_tf32(qg[(qr + 8) * D_ + kb * 8 + qc    ] * QS);
        qa[kb][2] = to_tf32(qg[(qr    ) * D_ + kb * 8 + qc + 4] * QS);
        qa[kb][3] = to_tf32(qg[(qr + 8) * D_ + kb * 8 + qc + 4] * QS);
    }

    float m0 = -INFINITY, m1 = -INFINITY, l0 = 0.f, l1 = 0.f;
    float of[10][4];
#pragma unroll
    for (int n = 0; n < 10; n++)
#pragma unroll
        for (int r = 0; r < 4; r++) of[n][r] = 0.f;

    auto load_tile = [&](int t, int buf) {
        const int kv0 = t * BNK;
#pragma unroll
        for (int i = 0; i < 10; i++) {
            int idx = tid + i * 128;
            int r = idx / 20, c4 = (idx % 20) * 4;
            cp_async16(ks_s[buf] + (uint32_t)(r * KST + c4) * 4,
                       kg + (size_t)(kv0 + r) * D_ + c4);
            cp_async16(vs_s[buf] + (uint32_t)(r * VST + c4) * 4,
                       vg + (size_t)(kv0 + r) * D_ + c4);
        }
        cp_commit();
    };

    load_tile(0, 0);

    const int NT = S_ / BNK;
    for (int t = 0; t < NT; t++) {
        const int buf = t & 1;
        if (t + 1 < NT) {
            load_tile(t + 1, buf ^ 1);
            cp_wait<1>();
        } else {
            cp_wait<0>();
        }
        __syncthreads();

        const float* Ks = KsB + buf * KBUF;
        const float* Vs = VsB + buf * VBUF;

        float sf[8][4];
#pragma unroll
        for (int n = 0; n < 8; n++)
#pragma unroll
            for (int r = 0; r < 4; r++) sf[n][r] = 0.f;

#pragma unroll
        for (int kb = 0; kb < 10; kb++)
#pragma unroll
            for (int nb = 0; nb < 8; nb++) {
                float b0 = Ks[(nb * 8 + qr) * KST + kb * 8 + qc];
                float b1 = Ks[(nb * 8 + qr) * KST + kb * 8 + qc + 4];
                mma_tf32(sf[nb], qa[kb][0], qa[kb][1], qa[kb][2], qa[kb][3],
                         b0, b1);
            }

        float rmax0 = -INFINITY, rmax1 = -INFINITY;
#pragma unroll
        for (int nb = 0; nb < 8; nb++) {
            rmax0 = fmaxf(rmax0, fmaxf(sf[nb][0], sf[nb][1]));
            rmax1 = fmaxf(rmax1, fmaxf(sf[nb][2], sf[nb][3]));
        }
#pragma unroll
        for (int off = 1; off <= 2; off <<= 1) {
            rmax0 = fmaxf(rmax0, __shfl_xor_sync(0xffffffffu, rmax0, off));
            rmax1 = fmaxf(rmax1, __shfl_xor_sync(0xffffffffu, rmax1, off));
        }
        float mn0 = fmaxf(m0, rmax0), mn1 = fmaxf(m1, rmax1);
        float cr0 = ex2(m0 - mn0),    cr1 = ex2(m1 - mn1);
        m0 = mn0; m1 = mn1;

        float rs0 = 0.f, rs1 = 0.f;
#pragma unroll
        for (int nb = 0; nb < 8; nb++) {
            sf[nb][0] = ex2(sf[nb][0] - mn0); rs0 += sf[nb][0];
            sf[nb][1] = ex2(sf[nb][1] - mn0); rs0 += sf[nb][1];
            sf[nb][2] = ex2(sf[nb][2] - mn1); rs1 += sf[nb][2];
            sf[nb][3] = ex2(sf[nb][3] - mn1); rs1 += sf[nb][3];
        }
#pragma unroll
        for (int off = 1; off <= 2; off <<= 1) {
            rs0 += __shfl_xor_sync(0xffffffffu, rs0, off);
            rs1 += __shfl_xor_sync(0xffffffffu, rs1, off);
        }
        l0 = l0 * cr0 + rs0;
        l1 = l1 * cr1 + rs1;
#pragma unroll
        for (int n = 0; n < 10; n++) {
            of[n][0] *= cr0; of[n][1] *= cr0;
            of[n][2] *= cr1; of[n][3] *= cr1;
        }

#pragma unroll
        for (int nb = 0; nb < 8; nb++)
#pragma unroll
            for (int r = 0; r < 4; r++) sf[nb][r] = to_tf32(sf[nb][r]);

        const int srcA = (lane & ~3) | (qc >> 1);
        const int srcB = srcA + 2;
        const bool odd = qc & 1;
#pragma unroll
        for (int kk = 0; kk < 8; kk++) {
            float t00 = __shfl_sync(0xffffffffu, sf[kk][0], srcA);
            float t01 = __shfl_sync(0xffffffffu, sf[kk][1], srcA);
            float t10 = __shfl_sync(0xffffffffu, sf[kk][2], srcA);
            float t11 = __shfl_sync(0xffffffffu, sf[kk][3], srcA);
            float t20 = __shfl_sync(0xffffffffu, sf[kk][0], srcB);
            float t21 = __shfl_sync(0xffffffffu, sf[kk][1], srcB);
            float t30 = __shfl_sync(0xffffffffu, sf[kk][2], srcB);
            float t31 = __shfl_sync(0xffffffffu, sf[kk][3], srcB);
            float a0 = odd ? t01 : t00;
            float a1 = odd ? t11 : t10;
            float a2 = odd ? t21 : t20;
            float a3 = odd ? t31 : t30;
#pragma unroll
            for (int nb2 = 0; nb2 < 10; nb2++) {
                float b0 = Vs[(kk * 8 + qc    ) * VST + nb2 * 8 + qr];
                float b1 = Vs[(kk * 8 + qc + 4) * VST + nb2 * 8 + qr];
                mma_tf32(of[nb2], a0, a1, a2, a3, b0, b1);
            }
        }
        __syncthreads();
    }

    float inv0 = 1.0f / l0, inv1 = 1.0f / l1;
    float* og = g_attn + (size_t)(b * S_ + q0 + w * 16) * D_ + h * DH_;
#pragma unroll
    for (int nb2 = 0; nb2 < 10; nb2++) {
        int col = nb2 * 8 + qc * 2;
        *(float2*)(og + (qr    ) * D_ + col) =
            make_float2(of[nb2][0] * inv0, of[nb2][1] * inv0);
        *(float2*)(og + (qr + 8) * D_ + col) =
            make_float2(of[nb2][2] * inv1, of[nb2][3] * inv1);
    }
}

// ---------------------------------------------------------------------------
extern "C" void kernel_launch(void* const* d_in, const int* in_sizes, int n_in,
                              void* d_out, int out_size)
{
    const float* x   = (const float*)d_in[0];
    const float* enc = (const float*)d_in[1];
    const float* Wq  = (const float*)d_in[2];
    const float* Wk  = (const float*)d_in[3];
    const float* Wv  = (const float*)d_in[4];
    const float* Wo  = (const float*)d_in[5];
    const float* bo  = (const float*)d_in[6];
    float* out = (float*)d_out;

    float *qp, *kp, *vp, *ap;
    cudaGetSymbolAddress((void**)&qp, g_q);
    cudaGetSymbolAddress((void**)&kp, g_k);
    cudaGetSymbolAddress((void**)&vp, g_v);
    cudaGetSymbolAddress((void**)&ap, g_attn);
    __nv_bfloat16 *xh, *xl, *eh, *el, *th, *tl, *wh, *wl;
    cudaGetSymbolAddress((void**)&xh, g_xh);
    cudaGetSymbolAddress((void**)&xl, g_xl);
    cudaGetSymbolAddress((void**)&eh, g_eh);
    cudaGetSymbolAddress((void**)&el, g_el);
    cudaGetSymbolAddress((void**)&th, g_th);
    cudaGetSymbolAddress((void**)&tl, g_tl);
    cudaGetSymbolAddress((void**)&wh, g_wh);
    cudaGetSymbolAddress((void**)&wl, g_wl);

    cudaFuncSetAttribute(flash_attn_tc,
                         cudaFuncAttributeMaxDynamicSharedMemorySize, ATTN_SMEM);
    cudaFuncSetAttribute(gemm_bf16_pre,
                         cudaFuncAttributeMaxDynamicSharedMemorySize, GEMM_SMEM);

    const int SPLIT_GRID = (M_ * D_) / (256 * 4);   // 2560

    // 1. pre-split inputs + weights
    wsplit_kernel<<<dim3(D_/32, D_/32, 4), dim3(32, 8)>>>(Wq, Wk, Wv, Wo, wh, wl);
    asplit_kernel<<<SPLIT_GRID, 256>>>(x,   xh, xl);
    asplit_kernel<<<SPLIT_GRID, 256>>>(enc, eh, el);

    // 2. projections
    dim3 gg(D_ / GN, M_ / GM);   // (10, 32)
    gemm_bf16_pre<<<gg, 256, GEMM_SMEM>>>(
        xh, xl, wh + 0*(size_t)D_*D_, wl + 0*(size_t)D_*D_, nullptr, qp, 0);
    gemm_bf16_pre<<<gg, 256, GEMM_SMEM>>>(
        eh, el, wh + 1*(size_t)D_*D_, wl + 1*(size_t)D_*D_, nullptr, kp, 1);
    gemm_bf16_pre<<<gg, 256, GEMM_SMEM>>>(
        eh, el, wh + 2*(size_t)D_*D_, wl + 2*(size_t)D_*D_, nullptr, vp, 1);

    // 3. attention
    dim3 attn_grid(S_ / BMQ, H_, B_);    // (32, 8, 2)
    flash_attn_tc<<<attn_grid, 128, ATTN_SMEM>>>();

    // 4. output projection
    asplit_kernel<<<SPLIT_GRID, 256>>>(ap, th, tl);
    gemm_bf16_pre<<<gg, 256, GEMM_SMEM>>>(
        th, tl, wh + 3*(size_t)D_*D_, wl + 3*(size_t)D_*D_, bo, out, 0);
}